// round 1
// baseline (speedup 1.0000x reference)
#include <cuda_runtime.h>
#include <cuda_bf16.h>

#define NN 2048
#define NM1 2047
#define NSUP 1536
#define CLS 5

// ------------------- scratch (device globals, no allocs) -------------------
__device__ float g_xw[2 * NN * 32];     // X @ W per branch
__device__ float g_deg[2 * NN];
__device__ float g_dis[2 * NN];
__device__ float g_acc1[2 * NN * 32];   // partial A@(dis*xw)
__device__ float g_tefe[NN * 64];       // [te | fe]
__device__ float g_Aw[NN * NN];         // 16MB dense constructed graph
__device__ float g_degc[NN];
__device__ float g_disc[NN];
__device__ float g_fcw[NN * 128];       // feats @ Wc
__device__ float g_emb[NN * 128];       // partial Aw@(disc*fcw)
__device__ float g_cols[8];

// ------------------- zero accumulators -------------------
__global__ void k_zero() {
    int idx = blockIdx.x * blockDim.x + threadIdx.x;
    int stride = gridDim.x * blockDim.x;
    for (int i = idx; i < 2 * NN * 32; i += stride) g_acc1[i] = 0.f;
    for (int i = idx; i < 2 * NN; i += stride) g_deg[i] = 0.f;
    for (int i = idx; i < NN; i += stride) g_degc[i] = 0.f;
    for (int i = idx; i < NN * 128; i += stride) g_emb[i] = 0.f;
    if (idx < 8) g_cols[idx] = 0.f;
}

// ------------------- XW = X @ W  ([2048,256]@[256,32]) -------------------
__global__ void k_xw(const float* __restrict__ X0, const float* __restrict__ X1,
                     const float* __restrict__ W0, const float* __restrict__ W1) {
    int branch = blockIdx.y;
    const float* X = branch ? X1 : X0;
    const float* W = branch ? W1 : W0;
    __shared__ float Ws[256 * 32];
    __shared__ float Xs[64][33];
    for (int e = threadIdx.x; e < 256 * 32; e += 256) Ws[e] = W[e];
    int r0 = blockIdx.x * 64;
    int f = threadIdx.x & 31;
    int rg = threadIdx.x >> 5;  // 0..7
    float acc[8] = {};
    for (int k0 = 0; k0 < 256; k0 += 32) {
        __syncthreads();
        for (int e = threadIdx.x; e < 64 * 32; e += 256) {
            int i = e >> 5, kk = e & 31;
            Xs[i][kk] = X[(r0 + i) * 256 + k0 + kk];
        }
        __syncthreads();
#pragma unroll
        for (int kk = 0; kk < 32; kk++) {
            float wv = Ws[(k0 + kk) * 32 + f];
#pragma unroll
            for (int l = 0; l < 8; l++)
                acc[l] += Xs[rg + 8 * l][kk] * wv;
        }
    }
#pragma unroll
    for (int l = 0; l < 8; l++)
        g_xw[branch * NN * 32 + (r0 + rg + 8 * l) * 32 + f] = acc[l];
}

// ------------------- deg[c] = sum_r A[c,r] (structural edge layout) -------------------
__global__ void k_deg(const float* __restrict__ wt, const float* __restrict__ wf) {
    int branch = blockIdx.z;
    const float* w = branch ? wf : wt;
    int c = blockIdx.x * 256 + threadIdx.x;
    int r0 = blockIdx.y * 256;
    float s = 0.f;
    for (int r = r0; r < r0 + 256; r++) {
        if (r != c) s += w[r * NM1 + c - (c > r)];
    }
    atomicAdd(&g_deg[branch * NN + c], s);
}

__global__ void k_cols(const int* __restrict__ labels) {
    int i = blockIdx.x * blockDim.x + threadIdx.x;
    if (i < NN) g_cols[labels[i]] = 1.0f;
}

__global__ void k_dis() {
    int idx = blockIdx.x * blockDim.x + threadIdx.x;
    if (idx < 2 * NN) g_dis[idx] = rsqrtf(1.0f + g_deg[idx]);
}

// ------------------- partial  A @ (dis * xw)  [2048,2048]@[2048,32] -------------------
__global__ void k_gcn1(const float* __restrict__ wt, const float* __restrict__ wf) {
    int branch = blockIdx.z;
    const float* w = branch ? wf : wt;
    __shared__ float As[32][128];
    __shared__ float ys[32][32];
    int c0 = blockIdx.x * 128;
    int tid = threadIdx.x;
    int cl = tid & 127;
    int f0 = (tid >> 7) * 16;
    int rbase = blockIdx.y * 256;
    float acc[16] = {};
    for (int r0 = rbase; r0 < rbase + 256; r0 += 32) {
        __syncthreads();
        for (int e = tid; e < 32 * 128; e += 256) {
            int j = e >> 7, i = e & 127;
            int r = r0 + j, c = c0 + i;
            As[j][i] = (c == r) ? 0.f : w[r * NM1 + c - (c > r)];
        }
        for (int e = tid; e < 32 * 32; e += 256) {
            int j = e >> 5, f = e & 31;
            int r = r0 + j;
            ys[j][f] = g_dis[branch * NN + r] * g_xw[branch * NN * 32 + r * 32 + f];
        }
        __syncthreads();
#pragma unroll
        for (int j = 0; j < 32; j++) {
            float a = As[j][cl];
#pragma unroll
            for (int ff = 0; ff < 16; ff++)
                acc[ff] += a * ys[j][f0 + ff];
        }
    }
#pragma unroll
    for (int ff = 0; ff < 16; ff++)
        atomicAdd(&g_acc1[branch * NN * 32 + (c0 + cl) * 32 + f0 + ff], acc[ff]);
}

// ------------------- te/fe finalize: lrelu(dis*acc + dis^2*xw + b) -------------------
__global__ void k_fin1(const float* __restrict__ bt, const float* __restrict__ bf) {
    int idx = blockIdx.x * blockDim.x + threadIdx.x;  // 2048*64
    int c = idx >> 6;
    int q = idx & 63;
    int branch = q >> 5;
    int f = q & 31;
    float b = branch ? bf[f] : bt[f];
    float d = g_dis[branch * NN + c];
    float v = d * g_acc1[branch * NN * 32 + c * 32 + f]
            + d * d * g_xw[branch * NN * 32 + c * 32 + f] + b;
    g_tefe[c * 64 + q] = v > 0.f ? v : 0.01f * v;
}

// ------------------- fcw = feats @ Wc (one-hot folded analytically) -------------------
__global__ void k_fcw(const float* __restrict__ Wc) {
    __shared__ float Wcs[64 * 128];
    __shared__ float Ts[32][64];
    __shared__ float ohs[128];
    int tid = threadIdx.x;  // 128 threads
    int r0 = blockIdx.x * 32;
    for (int e = tid; e < 64 * 128; e += 128) Wcs[e] = Wc[e];
    {   // one-hot columns contribution
        float s = 0.f;
#pragma unroll
        for (int c = 0; c < CLS; c++) s += g_cols[c] * Wc[(64 + c) * 128 + tid];
        ohs[tid] = s;
    }
    for (int e = tid; e < 32 * 64; e += 128) {
        int i = e >> 6, k = e & 63;
        Ts[i][k] = g_tefe[(r0 + i) * 64 + k];
    }
    __syncthreads();
    int f = tid;
    for (int i = 0; i < 32; i++) {
        int r = r0 + i;
        float acc = (r < NSUP) ? ohs[f] : 0.f;
#pragma unroll
        for (int k = 0; k < 64; k++) acc += Ts[i][k] * Wcs[k * 128 + f];
        g_fcw[r * 128 + f] = acc;
    }
}

// ------------------- dist + Aw = 1/(dist+1e-5), fused row sums -------------------
__global__ void k_dist() {
    __shared__ __align__(16) float Si[32][68];
    __shared__ __align__(16) float Sj[32][68];
    int tid = threadIdx.x;
    int i0 = blockIdx.y * 32, j0 = blockIdx.x * 32;
    for (int e = tid; e < 32 * 64; e += 256) {
        int i = e >> 6, d = e & 63;
        Si[i][d] = g_tefe[(i0 + i) * 64 + d];
        Sj[i][d] = g_tefe[(j0 + i) * 64 + d];
    }
    __syncthreads();
    int jx = tid & 31;
    int iy = tid >> 5;  // 0..7
    float acc[4] = {};
#pragma unroll
    for (int d = 0; d < 64; d += 4) {
        float4 b = *(const float4*)&Sj[jx][d];
#pragma unroll
        for (int t = 0; t < 4; t++) {
            float4 a = *(const float4*)&Si[iy + 8 * t][d];
            acc[t] += fabsf(a.x - b.x) + fabsf(a.y - b.y)
                    + fabsf(a.z - b.z) + fabsf(a.w - b.w);
        }
    }
    int j = j0 + jx;
#pragma unroll
    for (int t = 0; t < 4; t++) {
        int i = i0 + iy + 8 * t;
        float v = (i == j) ? 0.f : __frcp_rn(acc[t] + 1e-5f);
        g_Aw[i * NN + j] = v;
        float s = v;
#pragma unroll
        for (int off = 16; off; off >>= 1)
            s += __shfl_down_sync(0xffffffffu, s, off);
        if (jx == 0) atomicAdd(&g_degc[i], s);
    }
}

__global__ void k_disc() {
    int idx = blockIdx.x * blockDim.x + threadIdx.x;
    if (idx < NN) g_disc[idx] = rsqrtf(1.0f + g_degc[idx]);
}

// ------------------- partial  Aw @ (disc * fcw)  [2048,2048]@[2048,128] -------------------
__global__ void k_gcn2() {
    __shared__ float Aws[32][65];
    __shared__ __align__(16) float y2s[32][128];
    int tid = threadIdx.x;
    int c0 = blockIdx.x * 64;
    int fq = tid & 31;        // f = fq*4 .. +3
    int cg = tid >> 5;        // c = cg*8 .. +7
    int rbase = blockIdx.y * 256;
    float acc[8][4] = {};
    for (int r0 = rbase; r0 < rbase + 256; r0 += 32) {
        __syncthreads();
        for (int e = tid; e < 32 * 64; e += 256) {
            int i = e >> 5, j = e & 31;
            Aws[j][i] = g_Aw[(c0 + i) * NN + r0 + j];
        }
        for (int e = tid; e < 32 * 128; e += 256) {
            int j = e >> 7, f = e & 127;
            int r = r0 + j;
            y2s[j][f] = g_disc[r] * g_fcw[r * 128 + f];
        }
        __syncthreads();
#pragma unroll
        for (int j = 0; j < 32; j++) {
            float4 bv = *(const float4*)&y2s[j][fq * 4];
#pragma unroll
            for (int t = 0; t < 8; t++) {
                float a = Aws[j][cg * 8 + t];
                acc[t][0] += a * bv.x;
                acc[t][1] += a * bv.y;
                acc[t][2] += a * bv.z;
                acc[t][3] += a * bv.w;
            }
        }
    }
#pragma unroll
    for (int t = 0; t < 8; t++) {
        int c = c0 + cg * 8 + t;
#pragma unroll
        for (int u = 0; u < 4; u++)
            atomicAdd(&g_emb[c * 128 + fq * 4 + u], acc[t][u]);
    }
}

// ------------------- epilogue: lrelu(disc*emb + disc^2*fcw + bc) @ Wo + bo -------------------
__global__ void k_out(const float* __restrict__ bc, const float* __restrict__ Wo,
                      const float* __restrict__ bo, float* __restrict__ out) {
    __shared__ float Wos[128 * CLS];
    int tid = threadIdx.x;
    for (int e = tid; e < 128 * CLS; e += 256) Wos[e] = Wo[e];
    __syncthreads();
    int wid = tid >> 5, l = tid & 31;
    int row = blockIdx.x * 8 + wid;
    float dc = g_disc[row], dc2 = dc * dc;
    float o[CLS] = {};
#pragma unroll
    for (int t = 0; t < 4; t++) {
        int f = l + 32 * t;
        float e = dc * g_emb[row * 128 + f] + dc2 * g_fcw[row * 128 + f] + bc[f];
        e = e > 0.f ? e : 0.01f * e;
#pragma unroll
        for (int q = 0; q < CLS; q++) o[q] += e * Wos[f * CLS + q];
    }
#pragma unroll
    for (int q = 0; q < CLS; q++) {
#pragma unroll
        for (int off = 16; off; off >>= 1)
            o[q] += __shfl_down_sync(0xffffffffu, o[q], off);
    }
    if (l == 0) {
#pragma unroll
        for (int q = 0; q < CLS; q++) out[row * CLS + q] = o[q] + bo[q];
    }
}

// ------------------- launch -------------------
extern "C" void kernel_launch(void* const* d_in, const int* in_sizes, int n_in,
                              void* d_out, int out_size) {
    // Inputs in metadata order, skipping size-1 scalar entries (num_classes, query_size).
    int cur = 0;
    auto nxt = [&]() -> const void* {
        while (cur < n_in && in_sizes[cur] == 1) cur++;
        return d_in[cur++];
    };
    const float* tf     = (const float*)nxt();  // time_features [2048,256]
    (void)nxt();                                 // edge_index (structural, unused)
    const float* tw     = (const float*)nxt();  // time_edge_weight [E]
    const float* ff     = (const float*)nxt();  // freq_features
    const float* fw     = (const float*)nxt();  // freq_edge_weight
    const int*   labels = (const int*)nxt();    // labels [2048]
    const float* Wt     = (const float*)nxt();
    const float* bt     = (const float*)nxt();
    const float* Wf     = (const float*)nxt();
    const float* bf     = (const float*)nxt();
    const float* Wc     = (const float*)nxt();
    const float* bc     = (const float*)nxt();
    const float* Wo     = (const float*)nxt();
    const float* bo     = (const float*)nxt();
    float* out = (float*)d_out;

    k_zero<<<512, 256>>>();
    k_xw<<<dim3(32, 2), 256>>>(tf, ff, Wt, Wf);
    k_deg<<<dim3(8, 8, 2), 256>>>(tw, fw);
    k_cols<<<8, 256>>>(labels);
    k_dis<<<16, 256>>>();
    k_gcn1<<<dim3(16, 8, 2), 256>>>(tw, fw);
    k_fin1<<<512, 256>>>(bt, bf);
    k_fcw<<<64, 128>>>(Wc);
    k_dist<<<dim3(64, 64), 256>>>();
    k_disc<<<8, 256>>>();
    k_gcn2<<<dim3(32, 8), 256>>>();
    k_out<<<256, 256>>>(bc, Wo, bo, out);
}

// round 2
// speedup vs baseline: 1.0739x; 1.0739x over previous
#include <cuda_runtime.h>
#include <cuda_bf16.h>

#define NN 2048
#define NM1 2047
#define NSUP 1536
#define CLS 5

typedef unsigned long long u64;

__device__ __forceinline__ u64 add2(u64 a, u64 b) {
    u64 d; asm("add.rn.f32x2 %0, %1, %2;" : "=l"(d) : "l"(a), "l"(b)); return d;
}
__device__ __forceinline__ u64 fma2(u64 a, u64 b, u64 c) {
    u64 d; asm("fma.rn.f32x2 %0, %1, %2, %3;" : "=l"(d) : "l"(a), "l"(b), "l"(c)); return d;
}
__device__ __forceinline__ float lo32(u64 v) { return __uint_as_float((unsigned)(v & 0xffffffffu)); }
__device__ __forceinline__ float hi32(u64 v) { return __uint_as_float((unsigned)(v >> 32)); }
__device__ __forceinline__ u64 dupf(float a) {
    unsigned u = __float_as_uint(a);
    return ((u64)u << 32) | u;
}

// ------------------- scratch (device globals, no allocs) -------------------
__device__ float g_xw[2 * NN * 32];
__device__ float g_deg[2 * NN];
__device__ float g_dis[2 * NN];
__device__ float g_acc1[2 * NN * 32];
__device__ float g_tefe[NN * 64];
__device__ float g_Aw[NN * NN];
__device__ float g_degc[NN];
__device__ float g_disc[NN];
__device__ float g_fcw[NN * 128];
__device__ float g_emb[NN * 128];
__device__ float g_cols[8];

// ------------------- zero accumulators + one-hot cols -------------------
__global__ void k_zero(const int* __restrict__ labels) {
    int idx = blockIdx.x * blockDim.x + threadIdx.x;
    int stride = gridDim.x * blockDim.x;
    for (int i = idx; i < 2 * NN * 32; i += stride) g_acc1[i] = 0.f;
    for (int i = idx; i < 2 * NN; i += stride) g_deg[i] = 0.f;
    for (int i = idx; i < NN; i += stride) g_degc[i] = 0.f;
    for (int i = idx; i < NN * 128; i += stride) g_emb[i] = 0.f;
    if (idx < 8) g_cols[idx] = 0.f;
}
__global__ void k_cols(const int* __restrict__ labels) {
    int i = blockIdx.x * blockDim.x + threadIdx.x;
    if (i < NN) g_cols[labels[i]] = 1.0f;
}

// ------------------- XW = X @ W  ([2048,256]@[256,32]) -------------------
__global__ void k_xw(const float* __restrict__ X0, const float* __restrict__ X1,
                     const float* __restrict__ W0, const float* __restrict__ W1) {
    int branch = blockIdx.y;
    const float* X = branch ? X1 : X0;
    const float* W = branch ? W1 : W0;
    __shared__ float Ws[256 * 32];
    __shared__ float Xs[64][33];
    for (int e = threadIdx.x; e < 256 * 32; e += 256) Ws[e] = W[e];
    int r0 = blockIdx.x * 64;
    int f = threadIdx.x & 31;
    int rg = threadIdx.x >> 5;
    float acc[8] = {};
    for (int k0 = 0; k0 < 256; k0 += 32) {
        __syncthreads();
        for (int e = threadIdx.x; e < 64 * 32; e += 256) {
            int i = e >> 5, kk = e & 31;
            Xs[i][kk] = X[(r0 + i) * 256 + k0 + kk];
        }
        __syncthreads();
#pragma unroll
        for (int kk = 0; kk < 32; kk++) {
            float wv = Ws[(k0 + kk) * 32 + f];
#pragma unroll
            for (int l = 0; l < 8; l++)
                acc[l] += Xs[rg + 8 * l][kk] * wv;
        }
    }
#pragma unroll
    for (int l = 0; l < 8; l++)
        g_xw[branch * NN * 32 + (r0 + rg + 8 * l) * 32 + f] = acc[l];
}

// ------------------- deg[c] = sum_r A[c,r] -------------------
__global__ void k_deg(const float* __restrict__ wt, const float* __restrict__ wf) {
    int branch = blockIdx.z;
    const float* w = branch ? wf : wt;
    int c = blockIdx.x * 256 + threadIdx.x;
    int r0 = blockIdx.y * 256;
    float s = 0.f;
    for (int r = r0; r < r0 + 256; r++) {
        if (r != c) s += w[r * NM1 + c - (c > r)];
    }
    atomicAdd(&g_deg[branch * NN + c], s);
}

__global__ void k_dis() {
    int idx = blockIdx.x * blockDim.x + threadIdx.x;
    if (idx < 2 * NN) g_dis[idx] = rsqrtf(1.0f + g_deg[idx]);
}

// ------------------- partial  A @ (dis * xw)  [2048,2048]@[2048,32], f32x2 -------------------
__global__ void k_gcn1(const float* __restrict__ wt, const float* __restrict__ wf) {
    int branch = blockIdx.z;
    const float* w = branch ? wf : wt;
    __shared__ u64 Asd[32][128];                       // duplicated (a,a) pairs
    __shared__ __align__(16) float ys[32][32];
    int c0 = blockIdx.x * 128;
    int tid = threadIdx.x;
    int cl = tid & 127;
    int f0 = (tid >> 7) * 16;
    int rbase = blockIdx.y * 256;
    u64 acc2[8] = {};
    for (int r0 = rbase; r0 < rbase + 256; r0 += 32) {
        __syncthreads();
        for (int e = tid; e < 32 * 128; e += 256) {
            int j = e >> 7, i = e & 127;
            int r = r0 + j, c = c0 + i;
            float a = (c == r) ? 0.f : w[r * NM1 + c - (c > r)];
            Asd[j][i] = dupf(a);
        }
        for (int e = tid; e < 32 * 32; e += 256) {
            int j = e >> 5, f = e & 31;
            int r = r0 + j;
            ys[j][f] = g_dis[branch * NN + r] * g_xw[branch * NN * 32 + r * 32 + f];
        }
        __syncthreads();
#pragma unroll
        for (int j = 0; j < 32; j++) {
            u64 aa = Asd[j][cl];
            const ulonglong2* yp = (const ulonglong2*)&ys[j][f0];
            ulonglong2 y01 = yp[0];
            ulonglong2 y23 = yp[1];
            acc2[0] = fma2(aa, y01.x, acc2[0]);
            acc2[1] = fma2(aa, y01.y, acc2[1]);
            acc2[2] = fma2(aa, y23.x, acc2[2]);
            acc2[3] = fma2(aa, y23.y, acc2[3]);
            const ulonglong2* yq = (const ulonglong2*)&ys[j][f0 + 8];
            ulonglong2 y45 = yq[0];
            ulonglong2 y67 = yq[1];
            acc2[4] = fma2(aa, y45.x, acc2[4]);
            acc2[5] = fma2(aa, y45.y, acc2[5]);
            acc2[6] = fma2(aa, y67.x, acc2[6]);
            acc2[7] = fma2(aa, y67.y, acc2[7]);
        }
    }
    float* dst = &g_acc1[branch * NN * 32 + (c0 + cl) * 32 + f0];
#pragma unroll
    for (int k = 0; k < 8; k++) {
        atomicAdd(dst + 2 * k, lo32(acc2[k]));
        atomicAdd(dst + 2 * k + 1, hi32(acc2[k]));
    }
}

// ------------------- te/fe finalize -------------------
__global__ void k_fin1(const float* __restrict__ bt, const float* __restrict__ bf) {
    int idx = blockIdx.x * blockDim.x + threadIdx.x;
    int c = idx >> 6;
    int q = idx & 63;
    int branch = q >> 5;
    int f = q & 31;
    float b = branch ? bf[f] : bt[f];
    float d = g_dis[branch * NN + c];
    float v = d * g_acc1[branch * NN * 32 + c * 32 + f]
            + d * d * g_xw[branch * NN * 32 + c * 32 + f] + b;
    g_tefe[c * 64 + q] = v > 0.f ? v : 0.01f * v;
}

// ------------------- fcw = feats @ Wc -------------------
__global__ void k_fcw(const float* __restrict__ Wc) {
    __shared__ float Wcs[64 * 128];
    __shared__ float Ts[16][64];
    __shared__ float ohs[128];
    int tid = threadIdx.x;  // 256
    int r0 = blockIdx.x * 16;
    for (int e = tid; e < 64 * 128; e += 256) Wcs[e] = Wc[e];
    if (tid < 128) {
        float s = 0.f;
#pragma unroll
        for (int c = 0; c < CLS; c++) s += g_cols[c] * Wc[(64 + c) * 128 + tid];
        ohs[tid] = s;
    }
    for (int e = tid; e < 16 * 64; e += 256) {
        int i = e >> 6, k = e & 63;
        Ts[i][k] = g_tefe[(r0 + i) * 64 + k];
    }
    __syncthreads();
    int f = tid & 127, rh = tid >> 7;
    for (int i = rh * 8; i < rh * 8 + 8; i++) {
        int r = r0 + i;
        float acc = (r < NSUP) ? ohs[f] : 0.f;
#pragma unroll
        for (int k = 0; k < 64; k++) acc += Ts[i][k] * Wcs[k * 128 + f];
        g_fcw[r * 128 + f] = acc;
    }
}

// ------------------- dist (symmetric) + Aw = 1/(dist+1e-5), fused row sums -------------------
__global__ void k_dist() {
    int bi = blockIdx.y, bj = blockIdx.x;
    if (bj < bi) return;
    bool diag = (bi == bj);
    __shared__ __align__(16) float Si[32][68];
    __shared__ __align__(16) float Sjn[32][68];   // negated j-rows
    __shared__ float Vt[32][33];                   // for mirrored coalesced write
    int tid = threadIdx.x;
    int i0 = bi * 32, j0 = bj * 32;
    for (int e = tid; e < 32 * 64; e += 256) {
        int i = e >> 6, d = e & 63;
        Si[i][d] = g_tefe[(i0 + i) * 64 + d];
        Sjn[i][d] = -g_tefe[(j0 + i) * 64 + d];
    }
    __syncthreads();
    int jx = tid & 31;
    int iy = tid >> 5;  // 0..7
    u64 acc2[4][2] = {};
#pragma unroll
    for (int d = 0; d < 64; d += 4) {
        ulonglong2 b = *(const ulonglong2*)&Sjn[jx][d];
#pragma unroll
        for (int t = 0; t < 4; t++) {
            ulonglong2 a = *(const ulonglong2*)&Si[iy + 8 * t][d];
            u64 s0 = add2(a.x, b.x) & 0x7FFFFFFF7FFFFFFFULL;
            u64 s1 = add2(a.y, b.y) & 0x7FFFFFFF7FFFFFFFULL;
            acc2[t][0] = add2(acc2[t][0], s0);
            acc2[t][1] = add2(acc2[t][1], s1);
        }
    }
    int j = j0 + jx;
    float colpart = 0.f;
#pragma unroll
    for (int t = 0; t < 4; t++) {
        int i = i0 + iy + 8 * t;
        float dist = (lo32(acc2[t][0]) + hi32(acc2[t][0]))
                   + (lo32(acc2[t][1]) + hi32(acc2[t][1]));
        float v = (i == j) ? 0.f : __frcp_rn(dist + 1e-5f);
        g_Aw[i * NN + j] = v;
        Vt[jx][iy + 8 * t] = v;
        float s = v;
#pragma unroll
        for (int off = 16; off; off >>= 1)
            s += __shfl_down_sync(0xffffffffu, s, off);
        if (jx == 0) atomicAdd(&g_degc[i], s);
        colpart += v;
    }
    if (!diag) {
        atomicAdd(&g_degc[j], colpart);
        __syncthreads();
#pragma unroll
        for (int t = 0; t < 4; t++) {
            int jj = iy + 8 * t;
            g_Aw[(j0 + jj) * NN + i0 + jx] = Vt[jj][jx];
        }
    }
}

__global__ void k_disc() {
    int idx = blockIdx.x * blockDim.x + threadIdx.x;
    if (idx < NN) g_disc[idx] = rsqrtf(1.0f + g_degc[idx]);
}

// ------------------- partial  Aw @ (disc * fcw)  [2048,2048]@[2048,128], f32x2 -------------------
__global__ void k_gcn2() {
    __shared__ u64 Awsd[32][65];                    // duplicated (a,a): [j][c-local]
    __shared__ __align__(16) float y2s[32][128];
    int tid = threadIdx.x;
    int c0 = blockIdx.x * 64;
    int fq = tid & 31;        // f = fq*4 .. +3
    int cg = tid >> 5;        // c = cg*8 .. +7
    int rbase = blockIdx.y * 256;
    u64 acc2[8][2] = {};
    for (int r0 = rbase; r0 < rbase + 256; r0 += 32) {
        __syncthreads();
        for (int e = tid; e < 32 * 64; e += 256) {
            int i = e >> 5, j = e & 31;
            Awsd[j][i] = dupf(g_Aw[(c0 + i) * NN + r0 + j]);
        }
        for (int e = tid; e < 32 * 128; e += 256) {
            int j = e >> 7, f = e & 127;
            int r = r0 + j;
            y2s[j][f] = g_disc[r] * g_fcw[r * 128 + f];
        }
        __syncthreads();
#pragma unroll
        for (int j = 0; j < 32; j++) {
            ulonglong2 bv = *(const ulonglong2*)&y2s[j][fq * 4];
#pragma unroll
            for (int t = 0; t < 8; t++) {
                u64 aa = Awsd[j][cg * 8 + t];
                acc2[t][0] = fma2(aa, bv.x, acc2[t][0]);
                acc2[t][1] = fma2(aa, bv.y, acc2[t][1]);
            }
        }
    }
#pragma unroll
    for (int t = 0; t < 8; t++) {
        int c = c0 + cg * 8 + t;
        float* dst = &g_emb[c * 128 + fq * 4];
        atomicAdd(dst + 0, lo32(acc2[t][0]));
        atomicAdd(dst + 1, hi32(acc2[t][0]));
        atomicAdd(dst + 2, lo32(acc2[t][1]));
        atomicAdd(dst + 3, hi32(acc2[t][1]));
    }
}

// ------------------- epilogue -------------------
__global__ void k_out(const float* __restrict__ bc, const float* __restrict__ Wo,
                      const float* __restrict__ bo, float* __restrict__ out) {
    __shared__ float Wos[128 * CLS];
    int tid = threadIdx.x;
    for (int e = tid; e < 128 * CLS; e += 256) Wos[e] = Wo[e];
    __syncthreads();
    int wid = tid >> 5, l = tid & 31;
    int row = blockIdx.x * 8 + wid;
    float dc = g_disc[row], dc2 = dc * dc;
    float o[CLS] = {};
#pragma unroll
    for (int t = 0; t < 4; t++) {
        int f = l + 32 * t;
        float e = dc * g_emb[row * 128 + f] + dc2 * g_fcw[row * 128 + f] + bc[f];
        e = e > 0.f ? e : 0.01f * e;
#pragma unroll
        for (int q = 0; q < CLS; q++) o[q] += e * Wos[f * CLS + q];
    }
#pragma unroll
    for (int q = 0; q < CLS; q++) {
#pragma unroll
        for (int off = 16; off; off >>= 1)
            o[q] += __shfl_down_sync(0xffffffffu, o[q], off);
    }
    if (l == 0) {
#pragma unroll
        for (int q = 0; q < CLS; q++) out[row * CLS + q] = o[q] + bo[q];
    }
}

// ------------------- launch -------------------
extern "C" void kernel_launch(void* const* d_in, const int* in_sizes, int n_in,
                              void* d_out, int out_size) {
    int cur = 0;
    auto nxt = [&]() -> const void* {
        while (cur < n_in && in_sizes[cur] == 1) cur++;
        return d_in[cur++];
    };
    const float* tf     = (const float*)nxt();
    (void)nxt();                                 // edge_index (structural, unused)
    const float* tw     = (const float*)nxt();
    const float* ff     = (const float*)nxt();
    const float* fw     = (const float*)nxt();
    const int*   labels = (const int*)nxt();
    const float* Wt     = (const float*)nxt();
    const float* bt     = (const float*)nxt();
    const float* Wf     = (const float*)nxt();
    const float* bf     = (const float*)nxt();
    const float* Wc     = (const float*)nxt();
    const float* bc     = (const float*)nxt();
    const float* Wo     = (const float*)nxt();
    const float* bo     = (const float*)nxt();
    float* out = (float*)d_out;

    k_zero<<<512, 256>>>(labels);
    k_xw<<<dim3(32, 2), 256>>>(tf, ff, Wt, Wf);
    k_deg<<<dim3(8, 8, 2), 256>>>(tw, fw);
    k_cols<<<8, 256>>>(labels);
    k_dis<<<16, 256>>>();
    k_gcn1<<<dim3(16, 8, 2), 256>>>(tw, fw);
    k_fin1<<<512, 256>>>(bt, bf);
    k_fcw<<<128, 256>>>(Wc);
    k_dist<<<dim3(64, 64), 256>>>();
    k_disc<<<8, 256>>>();
    k_gcn2<<<dim3(32, 8), 256>>>();
    k_out<<<256, 256>>>(bc, Wo, bo, out);
}